// round 2
// baseline (speedup 1.0000x reference)
#include <cuda_runtime.h>
#include <cuda_bf16.h>

// Accumulator lives in device global memory (no allocations allowed).
__device__ float g_ce_sum;

__global__ void ce_init_kernel() {
    g_ce_sum = 0.0f;
}

// Gather + log + reduce. Each thread processes ITEMS rows with independent
// loads batched for MLP: ITEMS label loads issued back-to-back, then ITEMS gathers.
template <int ITEMS>
__global__ void ce_gather_kernel(const float* __restrict__ predicts,
                                 const int* __restrict__ labels,
                                 int n) {
    const int tid0 = blockIdx.x * blockDim.x + threadIdx.x;
    const int stride = gridDim.x * blockDim.x;

    float local = 0.0f;

    int idx[ITEMS];
    int lbl[ITEMS];
    bool valid[ITEMS];

#pragma unroll
    for (int j = 0; j < ITEMS; j++) {
        idx[j] = tid0 + j * stride;
        valid[j] = idx[j] < n;
    }
#pragma unroll
    for (int j = 0; j < ITEMS; j++) {
        lbl[j] = valid[j] ? __ldg(&labels[idx[j]]) : 0;
    }

    float p[ITEMS];
#pragma unroll
    for (int j = 0; j < ITEMS; j++) {
        p[j] = valid[j] ? __ldg(&predicts[(size_t)idx[j] * 128u + (unsigned)lbl[j]]) : 1.0f;
    }
#pragma unroll
    for (int j = 0; j < ITEMS; j++) {
        local += __logf(p[j]);
    }

    // Warp reduction
#pragma unroll
    for (int o = 16; o > 0; o >>= 1)
        local += __shfl_xor_sync(0xffffffffu, local, o);

    __shared__ float smem[32];
    const int lane = threadIdx.x & 31;
    const int wid = threadIdx.x >> 5;
    if (lane == 0) smem[wid] = local;
    __syncthreads();

    if (wid == 0) {
        const int nwarps = blockDim.x >> 5;
        local = (lane < nwarps) ? smem[lane] : 0.0f;
#pragma unroll
        for (int o = 16; o > 0; o >>= 1)
            local += __shfl_xor_sync(0xffffffffu, local, o);
        if (lane == 0) atomicAdd(&g_ce_sum, local);
    }
}

__global__ void ce_finalize_kernel(float* __restrict__ out, float inv_n) {
    *out = -g_ce_sum * inv_n;
}

extern "C" void kernel_launch(void* const* d_in, const int* in_sizes, int n_in,
                              void* d_out, int out_size) {
    // Identify inputs by element count: predicts has N*C elements, labels has N.
    int pi = 0, li = 1;
    if (n_in >= 2 && in_sizes[1] > in_sizes[0]) { pi = 1; li = 0; }

    const float* predicts = (const float*)d_in[pi];
    const int* labels = (const int*)d_in[li];
    float* out = (float*)d_out;

    const int n = in_sizes[li];  // number of rows

    constexpr int ITEMS = 8;
    constexpr int THREADS = 256;
    const int total_threads = (n + ITEMS - 1) / ITEMS;
    const int blocks = (total_threads + THREADS - 1) / THREADS;

    ce_init_kernel<<<1, 1>>>();
    ce_gather_kernel<ITEMS><<<blocks, THREADS>>>(predicts, labels, n);
    ce_finalize_kernel<<<1, 1>>>(out, 1.0f / (float)n);
}

// round 3
// speedup vs baseline: 1.0816x; 1.0816x over previous
#include <cuda_runtime.h>
#include <cuda_bf16.h>

// Device-global accumulators (zero-initialized at module load; the last block
// resets them after each run so graph replays stay deterministic).
__device__ float g_ce_sum;
__device__ unsigned int g_ticket;

template <int ITEMS>
__global__ void ce_fused_kernel(const float* __restrict__ predicts,
                                const int* __restrict__ labels,
                                float* __restrict__ out,
                                int n, float inv_n) {
    constexpr int VEC = ITEMS / 4;  // int4 label loads per thread
    const int tid0 = blockIdx.x * blockDim.x + threadIdx.x;
    const int stride = gridDim.x * blockDim.x;
    const int n4 = n >> 2;  // full int4 groups

    float local = 0.0f;

    // --- main vectorized part ---
    int v[VEC];
    int4 lbl[VEC];
    bool valid[VEC];
#pragma unroll
    for (int j = 0; j < VEC; j++) {
        v[j] = tid0 + j * stride;
        valid[j] = v[j] < n4;
    }
#pragma unroll
    for (int j = 0; j < VEC; j++) {
        lbl[j] = valid[j] ? __ldg(&((const int4*)labels)[v[j]])
                          : make_int4(0, 0, 0, 0);
    }

    float p[ITEMS];
#pragma unroll
    for (int j = 0; j < VEC; j++) {
        const size_t rb = (size_t)v[j] * 4u * 128u;
        p[4 * j + 0] = valid[j] ? __ldg(&predicts[rb + 0 * 128u + (unsigned)lbl[j].x]) : 1.0f;
        p[4 * j + 1] = valid[j] ? __ldg(&predicts[rb + 1 * 128u + (unsigned)lbl[j].y]) : 1.0f;
        p[4 * j + 2] = valid[j] ? __ldg(&predicts[rb + 2 * 128u + (unsigned)lbl[j].z]) : 1.0f;
        p[4 * j + 3] = valid[j] ? __ldg(&predicts[rb + 3 * 128u + (unsigned)lbl[j].w]) : 1.0f;
    }
#pragma unroll
    for (int j = 0; j < ITEMS; j++) {
        local += __logf(p[j]);
    }

    // --- scalar tail (rows n4*4 .. n-1), handled by first few threads ---
    const int tail = n - (n4 << 2);
    if (tid0 < tail) {
        const int row = (n4 << 2) + tid0;
        local += __logf(__ldg(&predicts[(size_t)row * 128u + (unsigned)__ldg(&labels[row])]));
    }

    // --- warp reduce ---
#pragma unroll
    for (int o = 16; o > 0; o >>= 1)
        local += __shfl_xor_sync(0xffffffffu, local, o);

    // --- block reduce ---
    __shared__ float smem[32];
    const int lane = threadIdx.x & 31;
    const int wid = threadIdx.x >> 5;
    if (lane == 0) smem[wid] = local;
    __syncthreads();

    __shared__ bool s_last;
    if (wid == 0) {
        const int nwarps = blockDim.x >> 5;
        local = (lane < nwarps) ? smem[lane] : 0.0f;
#pragma unroll
        for (int o = 16; o > 0; o >>= 1)
            local += __shfl_xor_sync(0xffffffffu, local, o);
        if (lane == 0) {
            atomicAdd(&g_ce_sum, local);
            __threadfence();
            unsigned int old = atomicAdd(&g_ticket, 1u);
            s_last = (old == gridDim.x - 1);
        }
    }
    __syncthreads();

    // --- last block finalizes and resets for the next (graph replay) run ---
    if (s_last && threadIdx.x == 0) {
        __threadfence();
        float total = g_ce_sum;
        *out = -total * inv_n;
        g_ce_sum = 0.0f;
        g_ticket = 0u;
    }
}

extern "C" void kernel_launch(void* const* d_in, const int* in_sizes, int n_in,
                              void* d_out, int out_size) {
    // Identify inputs by element count: predicts has N*C elements, labels has N.
    int pi = 0, li = 1;
    if (n_in >= 2 && in_sizes[1] > in_sizes[0]) { pi = 1; li = 0; }

    const float* predicts = (const float*)d_in[pi];
    const int* labels = (const int*)d_in[li];
    float* out = (float*)d_out;

    const int n = in_sizes[li];

    constexpr int ITEMS = 8;   // rows per thread (2x int4 label loads)
    constexpr int THREADS = 256;
    const int n4 = n >> 2;
    const int total_threads = (n4 + (ITEMS / 4) - 1) / (ITEMS / 4);
    int blocks = (total_threads + THREADS - 1) / THREADS;
    if (blocks < 1) blocks = 1;

    ce_fused_kernel<ITEMS><<<blocks, THREADS>>>(predicts, labels, out, n,
                                                1.0f / (float)n);
}